// round 14
// baseline (speedup 1.0000x reference)
#include <cuda_runtime.h>
#include <cuda_fp16.h>
#include <cstdint>
#include <math.h>

#define NN 50000
#define KK 16
#define EE 800000
#define BBATCH 1024
#define MAXM 48
#define FD 9
#define AD 10
#define HH 64
#define NEGINF (-1e9f)
#define NB_EMB 3126              // ceil((NN+1)/16)
#define NB_ELOG 3125             // EE/256

__device__ __forceinline__ unsigned pack_half2(float a, float b) {
    __half2 h = __floats2half2_rn(a, b);
    return *reinterpret_cast<unsigned*>(&h);
}
__device__ __forceinline__ float2 unpack_half2(unsigned u) {
    __half2 h = *reinterpret_cast<__half2*>(&u);
    return __half22float2(h);
}

// ---------------- scratch ------------------------------------------------------
__device__ uint2  d_hp0h[(NN + 1) * 16];   // fp16 node embeddings (row 0 = 0)
__device__ uint2  d_th1h[(NN + 1) * 16];   // fp16 hp1 @ Wg
__device__ uint2  d_tm1h[(NN + 1) * 16];   // fp16 hp1 @ Wm
__device__ uint2  d_hp2h[(NN + 1) * 16];   // fp16 hp2
__device__ float d_gp0[NN + 1];
__device__ float d_gp1[NN + 1];
__device__ float d_gm1[NN + 1];
__device__ float d_elog[EE];
__device__ uint2  d_accAh[NN * 16];        // fp16 aggregated neighbor feats
__device__ float d_accX16[NN * 16];
__device__ float4 d_p4[16];
__device__ float4 d_q4[16];
__device__ float d_qd[AD];
__device__ float d_c;
__device__ float d_wep[FD];      // We @ p
__device__ float d_c0;           // be . p
__device__ float4 d_M14[AD * 16];
__device__ float4 d_bm4[16];

// ---------------- constants (5 blocks) ------------------------------------------
__global__ __launch_bounds__(256) void k_consts(const float* __restrict__ Wg,
                                                const float* __restrict__ Wm,
                                                const float* __restrict__ a,
                                                const float* __restrict__ Wd,
                                                const float* __restrict__ bd,
                                                const float* __restrict__ We,
                                                const float* __restrict__ be) {
    int t = threadIdx.x;
    if (blockIdx.x == 0) {
        __shared__ float sp[HH], sq[HH];
        if (t < HH) {
            float p = 0.f, q = 0.f;
            #pragma unroll 8
            for (int i = 0; i < HH; i++) {
                p += Wg[t * HH + i] * a[i];
                q += Wm[t * HH + i] * a[HH + i];
            }
            sp[t] = p; sq[t] = q;
            ((float*)d_p4)[t] = p;
            ((float*)d_q4)[t] = q;
        }
        __syncthreads();
        if (t < AD) {
            float s = 0.f;
            for (int i = 0; i < HH; i++) s += Wd[t * HH + i] * sq[i];
            d_qd[t] = s;
        } else if (t == AD) {
            float s = 0.f;
            for (int i = 0; i < HH; i++) s += bd[i] * sq[i];
            d_c = s;
        } else if (t >= 32 && t < 32 + FD) {
            int r = t - 32;
            float s = 0.f;
            for (int j = 0; j < HH; j++) s += We[r * HH + j] * sp[j];
            d_wep[r] = s;
        } else if (t == 32 + FD) {
            float s = 0.f;
            for (int j = 0; j < HH; j++) s += be[j] * sp[j];
            d_c0 = s;
        }
        if (t < HH) {
            float s = 0.f;
            for (int i = 0; i < HH; i++) s += bd[i] * Wm[i * HH + t];
            ((float*)d_bm4)[t] = s;
        }
    } else {
        int idx = (blockIdx.x - 1) * 160 + t;
        if (t < 160 && idx < AD * HH) {
            int r = idx >> 6, j = idx & 63;
            float s = 0.f;
            #pragma unroll 8
            for (int i = 0; i < HH; i++) s += Wd[r * HH + i] * Wm[i * HH + j];
            ((float*)d_M14)[idx] = s;
        }
    }
}

// ---------------- fused embed (+gp0, fp16 hp0) and per-edge logit ----------------
__global__ __launch_bounds__(256) void k_pre(const float* __restrict__ tf,
                                             const float* __restrict__ We,
                                             const float* __restrict__ be,
                                             const float* __restrict__ fdg,
                                             const float* __restrict__ rij) {
    int b = blockIdx.x;
    if (b < NB_EMB) {
        int t = threadIdx.x, w = t >> 5, l = t & 31, sub = l & 15, half = l >> 4;
        int row = b * 16 + w * 2 + half;
        if (row > NN) return;
        float4 acc = make_float4(0.f, 0.f, 0.f, 0.f);
        float g = 0.f;
        if (row > 0) {
            int n = row - 1;
            const float* r = tf + n * FD;
            acc = ((const float4*)be)[sub];
            g = d_c0;
            #pragma unroll
            for (int tt = 0; tt < FD; tt++) {
                float x = __ldg(r + tt);
                float4 ww = ((const float4*)We)[tt * 16 + sub];
                acc.x += x * ww.x; acc.y += x * ww.y; acc.z += x * ww.z; acc.w += x * ww.w;
                g += x * d_wep[tt];
            }
        }
        uint2 pk;
        pk.x = pack_half2(acc.x, acc.y);
        pk.y = pack_half2(acc.z, acc.w);
        d_hp0h[row * 16 + sub] = pk;
        if (sub == 0) d_gp0[row] = g;
    } else {
        int e = (b - NB_EMB) * 256 + threadIdx.x;
        if (e >= EE) return;
        float s = d_c + rij[e] * d_qd[9];
        const float* x = fdg + (long)e * FD;
        #pragma unroll
        for (int r = 0; r < FD; r++) s += x[r] * d_qd[r];
        d_elog[e] = s;
    }
}

// ---------------- softmax helper (width 16) --------------------------------------
__device__ __forceinline__ float softmax16(float logit) {
    float mx = logit;
    #pragma unroll
    for (int m = 8; m; m >>= 1) mx = fmaxf(mx, __shfl_xor_sync(0xffffffffu, mx, m, 16));
    float ex = __expf(logit - mx);
    float sum = ex;
    #pragma unroll
    for (int m = 8; m; m >>= 1) sum += __shfl_xor_sync(0xffffffffu, sum, m, 16);
    return ex / sum;
}

// ---------------- fused alpha + gather, iteration 1 (fp16 in, fp16 out) ----------
__global__ __launch_bounds__(256) void k_gather1(const int* __restrict__ se,
                                                 const int* __restrict__ bs,
                                                 const float* __restrict__ fdg,
                                                 const float* __restrict__ rij) {
    __shared__ float4 sbc[8][2][17];
    int t = threadIdx.x, w = t >> 5, l = t & 31, sub = l & 15, half = l >> 4;
    int n = (blockIdx.x * 8 + w) * 2 + half;     // < NN exactly

    int idx = se[n * KK + sub];
    int e   = bs[n * KK + sub];
    float v = __ldg(&d_gp0[idx]) + __ldg(&d_elog[e]);
    v = (v > 0.f) ? v : 0.2f * v;
    float alpha = softmax16((idx == 0) ? NEGINF : v);

    sbc[w][half][sub] = make_float4(alpha, __int_as_float(idx), __int_as_float(e), 0.f);
    __syncwarp();

    float4 acc = make_float4(0.f, 0.f, 0.f, 0.f);
    float ax = 0.f;
    #pragma unroll
    for (int k = 0; k < KK; k++) {
        float4 b = sbc[w][half][k];
        int i  = __float_as_int(b.y);
        int ee = __float_as_int(b.z);
        uint2 hv = d_hp0h[i * 16 + sub];
        float2 vA = unpack_half2(hv.x), vB = unpack_half2(hv.y);
        acc.x += b.x * vA.x; acc.y += b.x * vA.y;
        acc.z += b.x * vB.x; acc.w += b.x * vB.y;
        if (sub < AD) {
            float x = (sub < FD) ? fdg[(long)ee * FD + sub] : rij[ee];
            ax += b.x * x;
        }
    }
    uint2 pk;
    pk.x = pack_half2(acc.x, acc.y);
    pk.y = pack_half2(acc.z, acc.w);
    d_accAh[n * 16 + sub] = pk;
    d_accX16[n * 16 + sub] = ax;
}

#define ELU1(x) ((x) > 0.f ? (x) : expm1f(x))
#define ELU4(o) \
    o.x = (o.x > 0.f) ? o.x : expm1f(o.x); \
    o.y = (o.y > 0.f) ? o.y : expm1f(o.y); \
    o.z = (o.z > 0.f) ? o.z : expm1f(o.z); \
    o.w = (o.w > 0.f) ? o.w : expm1f(o.w);

// ---------------- half2 GEMM pass helper -----------------------------------------
// 2 nodes x 8 channels per thread; accumulate 16-k groups in half2, spill to fp32.
__device__ __forceinline__ void gemm_pass_h(const unsigned* __restrict__ sW2,
                                            const __half* __restrict__ sacc,
                                            int r0, int r1, int ch8,
                                            float2 a0[4], float2 a1[4]) {
    #pragma unroll
    for (int grp = 0; grp < 4; grp++) {
        __half2 p0[4], p1[4];
        __half2 z = __floats2half2_rn(0.f, 0.f);
        #pragma unroll
        for (int c = 0; c < 4; c++) { p0[c] = z; p1[c] = z; }
        #pragma unroll
        for (int k8 = 0; k8 < 2; k8++) {
            int kbase = grp * 16 + k8 * 8;
            uint4 av0 = *(const uint4*)(sacc + r0 * 72 + kbase);
            uint4 av1 = *(const uint4*)(sacc + r1 * 72 + kbase);
            const unsigned* wrow = sW2 + kbase * 32 + ch8 * 4;
            #pragma unroll
            for (int kk = 0; kk < 4; kk++) {
                uint4 w_e = *(const uint4*)(wrow + (2 * kk) * 32);
                uint4 w_o = *(const uint4*)(wrow + (2 * kk + 1) * 32);
                __half2 ap0 = *(__half2*)(&av0.x + kk);
                __half2 ap1 = *(__half2*)(&av1.x + kk);
                __half2 b0l = __half2half2(__low2half(ap0));
                __half2 b0h = __half2half2(__high2half(ap0));
                __half2 b1l = __half2half2(__low2half(ap1));
                __half2 b1h = __half2half2(__high2half(ap1));
                const __half2* we = (const __half2*)&w_e;
                const __half2* wo = (const __half2*)&w_o;
                #pragma unroll
                for (int c = 0; c < 4; c++) {
                    p0[c] = __hfma2(b0l, we[c], p0[c]);
                    p0[c] = __hfma2(b0h, wo[c], p0[c]);
                    p1[c] = __hfma2(b1l, we[c], p1[c]);
                    p1[c] = __hfma2(b1h, wo[c], p1[c]);
                }
            }
        }
        #pragma unroll
        for (int c = 0; c < 4; c++) {
            float2 f0 = __half22float2(p0[c]);
            float2 f1 = __half22float2(p1[c]);
            a0[c].x += f0.x; a0[c].y += f0.y;
            a1[c].x += f1.x; a1[c].y += f1.y;
        }
    }
}

// ---------------- mega GEMM (HFMA2): hp1 = ELU(accA@Wg + accX@M1 + bm);
//                  th1 = hp1@Wg; tm1 = hp1@Wm; gp1/gm1 scalars --------------------
// smem: sWg2 8K + sWm2 8K + sacc 9K + sax 4.25K = 29.25 KiB
__global__ __launch_bounds__(256, 4) void k_mega(const float* __restrict__ Wg,
                                                 const float* __restrict__ Wm) {
    __shared__ unsigned sWg2[2048];
    __shared__ unsigned sWm2[2048];
    __shared__ __half sacc[64 * 72];     // row stride 72 halves = 144 B
    __shared__ float sax[64 * 17];

    int t = threadIdx.x;
    int nb0 = blockIdx.x * 64;
    for (int i = t; i < 2048; i += 256) {
        int k = i >> 5, c2 = i & 31;
        float2 g2 = ((const float2*)Wg)[k * 32 + c2];
        float2 m2 = ((const float2*)Wm)[k * 32 + c2];
        sWg2[i] = pack_half2(g2.x, g2.y);
        sWm2[i] = pack_half2(m2.x, m2.y);
    }
    for (int i = t; i < 1024; i += 256) {
        int node = i >> 4, s = i & 15, n = nb0 + node;
        uint2 hv = (n < NN) ? d_accAh[n * 16 + s] : make_uint2(0u, 0u);
        *(uint2*)((char*)sacc + node * 144 + s * 8) = hv;
    }
    for (int i = t; i < 1024; i += 256) {
        int node = i >> 4, r = i & 15, n = nb0 + node;
        sax[node * 17 + r] = (n < NN) ? d_accX16[n * 16 + r] : 0.f;
    }
    __syncthreads();

    int ch8 = t & 7, g = t >> 3;       // 8 channels x 2 nodes per thread
    int r0 = 2 * g, r1 = 2 * g + 1;
    int n0 = nb0 + r0, n1 = nb0 + r1;

    // ---- pass 1 ----
    float2 a0[4], a1[4];
    {
        float4 bA = __ldg(&d_bm4[ch8 * 2]);
        float4 bB = __ldg(&d_bm4[ch8 * 2 + 1]);
        a0[0] = make_float2(bA.x, bA.y); a0[1] = make_float2(bA.z, bA.w);
        a0[2] = make_float2(bB.x, bB.y); a0[3] = make_float2(bB.z, bB.w);
        #pragma unroll
        for (int c = 0; c < 4; c++) a1[c] = a0[c];
    }
    gemm_pass_h(sWg2, sacc, r0, r1, ch8, a0, a1);
    #pragma unroll
    for (int r = 0; r < AD; r++) {
        float4 mA = __ldg(&d_M14[r * 16 + ch8 * 2]);
        float4 mB = __ldg(&d_M14[r * 16 + ch8 * 2 + 1]);
        float x0 = sax[r0 * 17 + r], x1 = sax[r1 * 17 + r];
        a0[0].x += x0 * mA.x; a0[0].y += x0 * mA.y;
        a0[1].x += x0 * mA.z; a0[1].y += x0 * mA.w;
        a0[2].x += x0 * mB.x; a0[2].y += x0 * mB.y;
        a0[3].x += x0 * mB.z; a0[3].y += x0 * mB.w;
        a1[0].x += x1 * mA.x; a1[0].y += x1 * mA.y;
        a1[1].x += x1 * mA.z; a1[1].y += x1 * mA.w;
        a1[2].x += x1 * mB.x; a1[2].y += x1 * mB.y;
        a1[3].x += x1 * mB.z; a1[3].y += x1 * mB.w;
    }
    #pragma unroll
    for (int c = 0; c < 4; c++) {
        a0[c].x = ELU1(a0[c].x); a0[c].y = ELU1(a0[c].y);
        a1[c].x = ELU1(a1[c].x); a1[c].y = ELU1(a1[c].y);
    }
    // gp1/gm1: per-thread 8-channel dot, reduce across ch8 lanes (width 8)
    {
        float4 pA = __ldg(&d_p4[ch8 * 2]), pB = __ldg(&d_p4[ch8 * 2 + 1]);
        float4 qA = __ldg(&d_q4[ch8 * 2]), qB = __ldg(&d_q4[ch8 * 2 + 1]);
        float pp0 = a0[0].x*pA.x + a0[0].y*pA.y + a0[1].x*pA.z + a0[1].y*pA.w
                  + a0[2].x*pB.x + a0[2].y*pB.y + a0[3].x*pB.z + a0[3].y*pB.w;
        float pp1 = a1[0].x*pA.x + a1[0].y*pA.y + a1[1].x*pA.z + a1[1].y*pA.w
                  + a1[2].x*pB.x + a1[2].y*pB.y + a1[3].x*pB.z + a1[3].y*pB.w;
        float qq0 = a0[0].x*qA.x + a0[0].y*qA.y + a0[1].x*qA.z + a0[1].y*qA.w
                  + a0[2].x*qB.x + a0[2].y*qB.y + a0[3].x*qB.z + a0[3].y*qB.w;
        float qq1 = a1[0].x*qA.x + a1[0].y*qA.y + a1[1].x*qA.z + a1[1].y*qA.w
                  + a1[2].x*qB.x + a1[2].y*qB.y + a1[3].x*qB.z + a1[3].y*qB.w;
        #pragma unroll
        for (int m = 4; m; m >>= 1) {
            pp0 += __shfl_xor_sync(0xffffffffu, pp0, m, 8);
            pp1 += __shfl_xor_sync(0xffffffffu, pp1, m, 8);
            qq0 += __shfl_xor_sync(0xffffffffu, qq0, m, 8);
            qq1 += __shfl_xor_sync(0xffffffffu, qq1, m, 8);
        }
        if (ch8 == 0) {
            if (n0 < NN) { d_gp1[n0 + 1] = pp0; d_gm1[n0 + 1] = qq0; }
            if (n1 < NN) { d_gp1[n1 + 1] = pp1; d_gm1[n1 + 1] = qq1; }
        }
    }
    // write hp1 back into sacc rows (group-private; warp sync suffices)
    __syncwarp();
    {
        uint4 u0, u1;
        u0.x = pack_half2(a0[0].x, a0[0].y); u0.y = pack_half2(a0[1].x, a0[1].y);
        u0.z = pack_half2(a0[2].x, a0[2].y); u0.w = pack_half2(a0[3].x, a0[3].y);
        u1.x = pack_half2(a1[0].x, a1[0].y); u1.y = pack_half2(a1[1].x, a1[1].y);
        u1.z = pack_half2(a1[2].x, a1[2].y); u1.w = pack_half2(a1[3].x, a1[3].y);
        *(uint4*)((char*)sacc + r0 * 144 + ch8 * 16) = u0;
        *(uint4*)((char*)sacc + r1 * 144 + ch8 * 16) = u1;
    }
    __syncwarp();

    // ---- pass 2: th1 = hp1 @ Wg ----
    float2 b0[4], b1[4];
    #pragma unroll
    for (int c = 0; c < 4; c++) { b0[c] = make_float2(0.f, 0.f); b1[c] = b0[c]; }
    gemm_pass_h(sWg2, sacc, r0, r1, ch8, b0, b1);
    if (n0 < NN) {
        d_th1h[(n0 + 1) * 16 + ch8 * 2]     = make_uint2(pack_half2(b0[0].x, b0[0].y), pack_half2(b0[1].x, b0[1].y));
        d_th1h[(n0 + 1) * 16 + ch8 * 2 + 1] = make_uint2(pack_half2(b0[2].x, b0[2].y), pack_half2(b0[3].x, b0[3].y));
    }
    if (n1 < NN) {
        d_th1h[(n1 + 1) * 16 + ch8 * 2]     = make_uint2(pack_half2(b1[0].x, b1[0].y), pack_half2(b1[1].x, b1[1].y));
        d_th1h[(n1 + 1) * 16 + ch8 * 2 + 1] = make_uint2(pack_half2(b1[2].x, b1[2].y), pack_half2(b1[3].x, b1[3].y));
    }

    // ---- pass 3: tm1 = hp1 @ Wm ----
    #pragma unroll
    for (int c = 0; c < 4; c++) { b0[c] = make_float2(0.f, 0.f); b1[c] = b0[c]; }
    gemm_pass_h(sWm2, sacc, r0, r1, ch8, b0, b1);
    if (n0 < NN) {
        d_tm1h[(n0 + 1) * 16 + ch8 * 2]     = make_uint2(pack_half2(b0[0].x, b0[0].y), pack_half2(b0[1].x, b0[1].y));
        d_tm1h[(n0 + 1) * 16 + ch8 * 2 + 1] = make_uint2(pack_half2(b0[2].x, b0[2].y), pack_half2(b0[3].x, b0[3].y));
    }
    if (n1 < NN) {
        d_tm1h[(n1 + 1) * 16 + ch8 * 2]     = make_uint2(pack_half2(b1[0].x, b1[0].y), pack_half2(b1[1].x, b1[1].y));
        d_tm1h[(n1 + 1) * 16 + ch8 * 2 + 1] = make_uint2(pack_half2(b1[2].x, b1[2].y), pack_half2(b1[3].x, b1[3].y));
    }

    if (blockIdx.x == 0 && t < 16) {
        d_th1h[t] = make_uint2(0u, 0u);
        d_tm1h[t] = make_uint2(0u, 0u);
    }
    if (blockIdx.x == 0 && t == 0) { d_gp1[0] = 0.f; d_gm1[0] = 0.f; }
}

// ---------------- fused alpha + gather + ELU, iteration 2 (fp16 tables) ----------
__global__ __launch_bounds__(256) void k_gather2(const int* __restrict__ se,
                                                 const int* __restrict__ bs,
                                                 const int* __restrict__ su,
                                                 const int* __restrict__ sul) {
    __shared__ float4 sbc[8][2][17];
    int t = threadIdx.x, w = t >> 5, l = t & 31, sub = l & 15, half = l >> 4;
    int n = (blockIdx.x * 8 + w) * 2 + half;

    int idx = se[n * KK + sub];
    int e   = bs[n * KK + sub];
    int j   = __ldg(&su[e]);
    float msk = (__ldg(&sul[e]) > 0) ? 1.f : 0.f;
    float v = __ldg(&d_gp1[idx]) + msk * __ldg(&d_gm1[j]);
    v = (v > 0.f) ? v : 0.2f * v;
    float alpha = softmax16((idx == 0) ? NEGINF : v);

    sbc[w][half][sub] = make_float4(alpha, __int_as_float(idx), __int_as_float(j),
                                    alpha * msk);
    __syncwarp();

    float4 acc = make_float4(0.f, 0.f, 0.f, 0.f);
    #pragma unroll
    for (int k = 0; k < KK; k++) {
        float4 b = sbc[w][half][k];
        int i  = __float_as_int(b.y);
        int jj = __float_as_int(b.z);
        uint2 hv = d_th1h[i * 16 + sub];
        float2 vA = unpack_half2(hv.x), vB = unpack_half2(hv.y);
        acc.x += b.x * vA.x; acc.y += b.x * vA.y;
        acc.z += b.x * vB.x; acc.w += b.x * vB.y;
        uint2 hu = d_tm1h[jj * 16 + sub];
        float2 uA = unpack_half2(hu.x), uB = unpack_half2(hu.y);
        acc.x += b.w * uA.x; acc.y += b.w * uA.y;
        acc.z += b.w * uB.x; acc.w += b.w * uB.y;
    }
    ELU4(acc)
    uint2 pk;
    pk.x = pack_half2(acc.x, acc.y);
    pk.y = pack_half2(acc.z, acc.w);
    d_hp2h[(n + 1) * 16 + sub] = pk;
    if (blockIdx.x == 0 && t < 16) d_hp2h[t] = make_uint2(0u, 0u);
}

// ---------------- readout (fp16 hp2 -> fp32 out) ----------------------------------
__global__ __launch_bounds__(256) void k_out(const int* __restrict__ ls,
                                             float* __restrict__ out) {
    int wid = (blockIdx.x * blockDim.x + threadIdx.x) >> 5;
    int l = threadIdx.x & 31;
    int sub = l & 15;
    int mol = wid * 2 + (l >> 4);
    if (mol >= BBATCH) return;
    const int* row = ls + mol * MAXM;
    float4 acc = make_float4(0.f, 0.f, 0.f, 0.f);
    #pragma unroll 8
    for (int m = 0; m < MAXM; m++) {
        int i = __ldg(row + m);
        uint2 hv = d_hp2h[i * 16 + sub];
        float2 vA = unpack_half2(hv.x), vB = unpack_half2(hv.y);
        acc.x += vA.x; acc.y += vA.y; acc.z += vB.x; acc.w += vB.y;
    }
    ((float4*)out)[mol * 16 + sub] = acc;
}

// ---------------- launch -----------------------------------------------------------
extern "C" void kernel_launch(void* const* d_in, const int* in_sizes, int n_in,
                              void* d_out, int out_size) {
    const float* tf  = (const float*)d_in[0];
    const float* fdg = (const float*)d_in[1];
    const float* rij = (const float*)d_in[2];
    const int*   se  = (const int*)d_in[3];
    const int*   bs  = (const int*)d_in[4];
    const int*   ls  = (const int*)d_in[5];
    const int*   su  = (const int*)d_in[6];
    const int*   sul = (const int*)d_in[7];
    const float* We  = (const float*)d_in[8];
    const float* be  = (const float*)d_in[9];
    const float* Wd  = (const float*)d_in[10];
    const float* bd  = (const float*)d_in[11];
    const float* Wg  = (const float*)d_in[12];
    const float* Wm  = (const float*)d_in[13];
    const float* ag  = (const float*)d_in[14];

    int gat_blocks = NN / 16;               // 3125
    int gemm_blocks = (NN + 63) / 64;       // 782

    k_consts<<<5, 256>>>(Wg, Wm, ag, Wd, bd, We, be);
    k_pre<<<NB_EMB + NB_ELOG, 256>>>(tf, We, be, fdg, rij);

    k_gather1<<<gat_blocks, 256>>>(se, bs, fdg, rij);
    k_mega<<<gemm_blocks, 256>>>(Wg, Wm);
    k_gather2<<<gat_blocks, 256>>>(se, bs, su, sul);

    k_out<<<(BBATCH / 2 + 7) / 8, 256>>>(ls, (float*)d_out);
}

// round 15
// speedup vs baseline: 1.3397x; 1.3397x over previous
#include <cuda_runtime.h>
#include <cuda_fp16.h>
#include <cstdint>
#include <math.h>

#define NN 50000
#define KK 16
#define EE 800000
#define BBATCH 1024
#define MAXM 48
#define FD 9
#define AD 10
#define HH 64
#define NEGINF (-1e9f)
#define NB_G 196                 // ceil((NN+1)/256)
#define NB_ELOG 3125             // EE/256

__device__ __forceinline__ unsigned pack_half2(float a, float b) {
    __half2 h = __floats2half2_rn(a, b);
    return *reinterpret_cast<unsigned*>(&h);
}
__device__ __forceinline__ float2 unpack_half2(unsigned u) {
    __half2 h = *reinterpret_cast<__half2*>(&u);
    return __half22float2(h);
}

// ---------------- scratch ------------------------------------------------------
__device__ uint2  d_th1h[(NN + 1) * 16];   // fp16 hp1 @ Wg
__device__ uint2  d_tm1h[(NN + 1) * 16];   // fp16 hp1 @ Wm
__device__ uint2  d_hp2h[(NN + 1) * 16];   // fp16 hp2
__device__ float d_gp0[NN + 1];
__device__ float d_gp1[NN + 1];
__device__ float d_gm1[NN + 1];
__device__ float d_elog[EE];
__device__ float d_a9s[NN * 12];           // 9 aggregated tf feats + s + pad
__device__ float d_accX16[NN * 16];
__device__ float4 d_p4[16];
__device__ float4 d_q4[16];
__device__ float d_qd[AD];
__device__ float d_c;
__device__ float d_wep[FD];      // We @ p
__device__ float d_c0;           // be . p
__device__ float4 d_M14[AD * 16];  // Wd @ Wm
__device__ float4 d_bm4[16];       // bd @ Wm
__device__ float4 d_G94[FD * 16];  // We @ Wg
__device__ float4 d_gb4[16];       // be @ Wg

// ---------------- constants (9 blocks) ------------------------------------------
__global__ __launch_bounds__(256) void k_consts(const float* __restrict__ Wg,
                                                const float* __restrict__ Wm,
                                                const float* __restrict__ a,
                                                const float* __restrict__ Wd,
                                                const float* __restrict__ bd,
                                                const float* __restrict__ We,
                                                const float* __restrict__ be) {
    int t = threadIdx.x;
    int b = blockIdx.x;
    if (b == 0) {
        __shared__ float sp[HH], sq[HH];
        if (t < HH) {
            float p = 0.f, q = 0.f;
            #pragma unroll 8
            for (int i = 0; i < HH; i++) {
                p += Wg[t * HH + i] * a[i];
                q += Wm[t * HH + i] * a[HH + i];
            }
            sp[t] = p; sq[t] = q;
            ((float*)d_p4)[t] = p;
            ((float*)d_q4)[t] = q;
        }
        __syncthreads();
        if (t < AD) {
            float s = 0.f;
            for (int i = 0; i < HH; i++) s += Wd[t * HH + i] * sq[i];
            d_qd[t] = s;
        } else if (t == AD) {
            float s = 0.f;
            for (int i = 0; i < HH; i++) s += bd[i] * sq[i];
            d_c = s;
        } else if (t >= 32 && t < 32 + FD) {
            int r = t - 32;
            float s = 0.f;
            for (int j = 0; j < HH; j++) s += We[r * HH + j] * sp[j];
            d_wep[r] = s;
        } else if (t == 32 + FD) {
            float s = 0.f;
            for (int j = 0; j < HH; j++) s += be[j] * sp[j];
            d_c0 = s;
        }
        if (t < HH) {
            float s = 0.f;
            for (int i = 0; i < HH; i++) s += bd[i] * Wm[i * HH + t];
            ((float*)d_bm4)[t] = s;
        }
    } else if (b <= 4) {
        int idx = (b - 1) * 160 + t;
        if (t < 160 && idx < AD * HH) {
            int r = idx >> 6, j = idx & 63;
            float s = 0.f;
            #pragma unroll 8
            for (int i = 0; i < HH; i++) s += Wd[r * HH + i] * Wm[i * HH + j];
            ((float*)d_M14)[idx] = s;
        }
    } else {
        // blocks 5-8: G9 (576) + gb (64)
        int idx = (b - 5) * 160 + t;
        if (t < 160 && idx < FD * HH + HH) {
            if (idx < FD * HH) {
                int r = idx >> 6, j = idx & 63;
                float s = 0.f;
                #pragma unroll 8
                for (int i = 0; i < HH; i++) s += We[r * HH + i] * Wg[i * HH + j];
                ((float*)d_G94)[idx] = s;
            } else {
                int j = idx - FD * HH;
                float s = 0.f;
                #pragma unroll 8
                for (int i = 0; i < HH; i++) s += be[i] * Wg[i * HH + j];
                ((float*)d_gb4)[j] = s;
            }
        }
    }
}

// ---------------- fused gp0 and per-edge logit ------------------------------------
__global__ __launch_bounds__(256) void k_pre(const float* __restrict__ tf,
                                             const float* __restrict__ fdg,
                                             const float* __restrict__ rij) {
    int b = blockIdx.x;
    if (b < NB_G) {
        int row = b * 256 + threadIdx.x;
        if (row > NN) return;
        float g = 0.f;
        if (row > 0) {
            const float* r = tf + (row - 1) * FD;
            g = d_c0;
            #pragma unroll
            for (int tt = 0; tt < FD; tt++) g += __ldg(r + tt) * d_wep[tt];
        }
        d_gp0[row] = g;
    } else {
        int e = (b - NB_G) * 256 + threadIdx.x;
        if (e >= EE) return;
        float s = d_c + rij[e] * d_qd[9];
        const float* x = fdg + (long)e * FD;
        #pragma unroll
        for (int r = 0; r < FD; r++) s += x[r] * d_qd[r];
        d_elog[e] = s;
    }
}

// ---------------- softmax helper (width 16) --------------------------------------
__device__ __forceinline__ float softmax16(float logit) {
    float mx = logit;
    #pragma unroll
    for (int m = 8; m; m >>= 1) mx = fmaxf(mx, __shfl_xor_sync(0xffffffffu, mx, m, 16));
    float ex = __expf(logit - mx);
    float sum = ex;
    #pragma unroll
    for (int m = 8; m; m >>= 1) sum += __shfl_xor_sync(0xffffffffu, sum, m, 16);
    return ex / sum;
}

// ---------------- fused alpha + gather, iteration 1 (tf-level aggregation) --------
__global__ __launch_bounds__(256) void k_gather1(const int* __restrict__ se,
                                                 const int* __restrict__ bs,
                                                 const float* __restrict__ tf,
                                                 const float* __restrict__ fdg,
                                                 const float* __restrict__ rij) {
    __shared__ float4 sbc[8][2][17];
    int t = threadIdx.x, w = t >> 5, l = t & 31, sub = l & 15, half = l >> 4;
    int n = (blockIdx.x * 8 + w) * 2 + half;     // < NN exactly

    int idx = se[n * KK + sub];
    int e   = bs[n * KK + sub];
    float v = __ldg(&d_gp0[idx]) + __ldg(&d_elog[e]);
    v = (v > 0.f) ? v : 0.2f * v;
    float alpha = softmax16((idx == 0) ? NEGINF : v);

    float sflag = (idx != 0) ? alpha : 0.f;
    #pragma unroll
    for (int m = 8; m; m >>= 1) sflag += __shfl_xor_sync(0xffffffffu, sflag, m, 16);

    sbc[w][half][sub] = make_float4(alpha, __int_as_float(idx), __int_as_float(e), 0.f);
    __syncwarp();

    float a9 = 0.f, ax = 0.f;
    #pragma unroll
    for (int k = 0; k < KK; k++) {
        float4 b = sbc[w][half][k];
        int i  = __float_as_int(b.y);
        int ee = __float_as_int(b.z);
        if (sub < FD) {
            if (i > 0) a9 += b.x * __ldg(&tf[(long)(i - 1) * FD + sub]);
            ax += b.x * __ldg(&fdg[(long)ee * FD + sub]);
        } else if (sub == FD) {
            ax += b.x * __ldg(&rij[ee]);
        }
    }
    if (sub < FD) d_a9s[n * 12 + sub] = a9;
    else if (sub == FD) d_a9s[n * 12 + FD] = sflag;
    d_accX16[n * 16 + sub] = ax;
}

#define FMA4(o, a, w0, w1, w2, w3)                                     \
    o.x += a.x * w0.x + a.y * w1.x + a.z * w2.x + a.w * w3.x;          \
    o.y += a.x * w0.y + a.y * w1.y + a.z * w2.y + a.w * w3.y;          \
    o.z += a.x * w0.z + a.y * w1.z + a.z * w2.z + a.w * w3.z;          \
    o.w += a.x * w0.w + a.y * w1.w + a.z * w2.w + a.w * w3.w;

#define ELU4(o) \
    o.x = (o.x > 0.f) ? o.x : expm1f(o.x); \
    o.y = (o.y > 0.f) ? o.y : expm1f(o.y); \
    o.z = (o.z > 0.f) ? o.z : expm1f(o.z); \
    o.w = (o.w > 0.f) ? o.w : expm1f(o.w);

#define RANK1(o0, o1, o2, o3, m, x0, x1, x2, x3)                       \
    o0.x += x0 * m.x; o0.y += x0 * m.y; o0.z += x0 * m.z; o0.w += x0 * m.w; \
    o1.x += x1 * m.x; o1.y += x1 * m.y; o1.z += x1 * m.z; o1.w += x1 * m.w; \
    o2.x += x2 * m.x; o2.y += x2 * m.y; o2.z += x2 * m.z; o2.w += x2 * m.w; \
    o3.x += x3 * m.x; o3.y += x3 * m.y; o3.z += x3 * m.z; o3.w += x3 * m.w;

// ---------------- mega: hp1 = ELU(a9@G9 + s*gb + accX@M1 + bm);
//                  th1 = hp1@Wg; tm1 = hp1@Wm (fused, fp16 out); gp1/gm1 ---------
// dyn smem: sWg 16K + sWm 16K + sacc 17K + sa9 3K + sax 4.25K = 56.25 KiB
__global__ __launch_bounds__(256, 3) void k_mega(const float* __restrict__ Wg,
                                                 const float* __restrict__ Wm) {
    extern __shared__ float4 dyn[];
    float4* sWg = dyn;                       // 1024 float4
    float4* sWm = dyn + 1024;                // 1024 float4
    float*  sacc = (float*)(dyn + 2048);     // 64*68 (hp1)
    float*  sa9  = sacc + 64 * 68;           // 64*12
    float*  sax  = sa9 + 64 * 12;            // 64*17

    int t = threadIdx.x;
    int nb0 = blockIdx.x * 64;
    for (int i = t; i < HH * 16; i += 256) {
        sWg[i] = ((const float4*)Wg)[i];
        sWm[i] = ((const float4*)Wm)[i];
    }
    for (int i = t; i < 768; i += 256) {
        int node = i / 12, r = i % 12, n = nb0 + node;
        sa9[i] = (n < NN) ? d_a9s[n * 12 + r] : 0.f;
    }
    for (int i = t; i < 1024; i += 256) {
        int node = i >> 4, r = i & 15, n = nb0 + node;
        sax[node * 17 + r] = (n < NN) ? d_accX16[n * 16 + r] : 0.f;
    }
    __syncthreads();

    int ch = t & 15, g = t >> 4;
    int nl = g * 4;

    // ---- pass 1: hp1 = ELU(a9@G9 + s*gb + accX@M1 + bm) ----
    float4 bm = __ldg(&d_bm4[ch]);
    float4 o0 = bm, o1 = bm, o2 = bm, o3 = bm;
    {
        float4 gb = __ldg(&d_gb4[ch]);
        float s0 = sa9[(nl + 0) * 12 + FD], s1 = sa9[(nl + 1) * 12 + FD];
        float s2 = sa9[(nl + 2) * 12 + FD], s3 = sa9[(nl + 3) * 12 + FD];
        RANK1(o0, o1, o2, o3, gb, s0, s1, s2, s3)
    }
    #pragma unroll
    for (int r = 0; r < FD; r++) {
        float4 m = __ldg(&d_G94[r * 16 + ch]);
        float x0 = sa9[(nl + 0) * 12 + r], x1 = sa9[(nl + 1) * 12 + r];
        float x2 = sa9[(nl + 2) * 12 + r], x3 = sa9[(nl + 3) * 12 + r];
        RANK1(o0, o1, o2, o3, m, x0, x1, x2, x3)
    }
    #pragma unroll
    for (int r = 0; r < AD; r++) {
        float4 m = __ldg(&d_M14[r * 16 + ch]);
        float x0 = sax[(nl + 0) * 17 + r], x1 = sax[(nl + 1) * 17 + r];
        float x2 = sax[(nl + 2) * 17 + r], x3 = sax[(nl + 3) * 17 + r];
        RANK1(o0, o1, o2, o3, m, x0, x1, x2, x3)
    }
    ELU4(o0) ELU4(o1) ELU4(o2) ELU4(o3)

    // gp1/gm1 scalars
    {
        float4 p = __ldg(&d_p4[ch]), q = __ldg(&d_q4[ch]);
        float pp0 = o0.x*p.x + o0.y*p.y + o0.z*p.z + o0.w*p.w;
        float pp1 = o1.x*p.x + o1.y*p.y + o1.z*p.z + o1.w*p.w;
        float pp2 = o2.x*p.x + o2.y*p.y + o2.z*p.z + o2.w*p.w;
        float pp3 = o3.x*p.x + o3.y*p.y + o3.z*p.z + o3.w*p.w;
        float qq0 = o0.x*q.x + o0.y*q.y + o0.z*q.z + o0.w*q.w;
        float qq1 = o1.x*q.x + o1.y*q.y + o1.z*q.z + o1.w*q.w;
        float qq2 = o2.x*q.x + o2.y*q.y + o2.z*q.z + o2.w*q.w;
        float qq3 = o3.x*q.x + o3.y*q.y + o3.z*q.z + o3.w*q.w;
        #pragma unroll
        for (int m = 8; m; m >>= 1) {
            pp0 += __shfl_xor_sync(0xffffffffu, pp0, m, 16);
            pp1 += __shfl_xor_sync(0xffffffffu, pp1, m, 16);
            pp2 += __shfl_xor_sync(0xffffffffu, pp2, m, 16);
            pp3 += __shfl_xor_sync(0xffffffffu, pp3, m, 16);
            qq0 += __shfl_xor_sync(0xffffffffu, qq0, m, 16);
            qq1 += __shfl_xor_sync(0xffffffffu, qq1, m, 16);
            qq2 += __shfl_xor_sync(0xffffffffu, qq2, m, 16);
            qq3 += __shfl_xor_sync(0xffffffffu, qq3, m, 16);
        }
        if (ch == 0) {
            if (nb0 + nl + 0 < NN) { d_gp1[nb0 + nl + 1] = pp0; d_gm1[nb0 + nl + 1] = qq0; }
            if (nb0 + nl + 1 < NN) { d_gp1[nb0 + nl + 2] = pp1; d_gm1[nb0 + nl + 2] = qq1; }
            if (nb0 + nl + 2 < NN) { d_gp1[nb0 + nl + 3] = pp2; d_gm1[nb0 + nl + 3] = qq2; }
            if (nb0 + nl + 3 < NN) { d_gp1[nb0 + nl + 4] = pp3; d_gm1[nb0 + nl + 4] = qq3; }
        }
    }

    // write hp1 into own sacc rows — half-warp private, warp sync suffices
    __syncwarp();
    *(float4*)&sacc[(nl + 0) * 68 + ch * 4] = o0;
    *(float4*)&sacc[(nl + 1) * 68 + ch * 4] = o1;
    *(float4*)&sacc[(nl + 2) * 68 + ch * 4] = o2;
    *(float4*)&sacc[(nl + 3) * 68 + ch * 4] = o3;
    __syncwarp();

    // ---- fused passes 2+3: th1 = hp1@Wg, tm1 = hp1@Wm ----
    float4 uA0 = make_float4(0.f,0.f,0.f,0.f), uA1 = uA0, uA2 = uA0, uA3 = uA0;
    float4 uB0 = uA0, uB1 = uA0, uB2 = uA0, uB3 = uA0;
    #pragma unroll
    for (int s4 = 0; s4 < 16; s4++) {
        float4 a0 = *(float4*)&sacc[(nl + 0) * 68 + s4 * 4];
        float4 a1 = *(float4*)&sacc[(nl + 1) * 68 + s4 * 4];
        float4 a2 = *(float4*)&sacc[(nl + 2) * 68 + s4 * 4];
        float4 a3 = *(float4*)&sacc[(nl + 3) * 68 + s4 * 4];
        {
            float4 w0 = sWg[(4 * s4 + 0) * 16 + ch];
            float4 w1 = sWg[(4 * s4 + 1) * 16 + ch];
            float4 w2 = sWg[(4 * s4 + 2) * 16 + ch];
            float4 w3 = sWg[(4 * s4 + 3) * 16 + ch];
            FMA4(uA0, a0, w0, w1, w2, w3)
            FMA4(uA1, a1, w0, w1, w2, w3)
            FMA4(uA2, a2, w0, w1, w2, w3)
            FMA4(uA3, a3, w0, w1, w2, w3)
        }
        {
            float4 w0 = sWm[(4 * s4 + 0) * 16 + ch];
            float4 w1 = sWm[(4 * s4 + 1) * 16 + ch];
            float4 w2 = sWm[(4 * s4 + 2) * 16 + ch];
            float4 w3 = sWm[(4 * s4 + 3) * 16 + ch];
            FMA4(uB0, a0, w0, w1, w2, w3)
            FMA4(uB1, a1, w0, w1, w2, w3)
            FMA4(uB2, a2, w0, w1, w2, w3)
            FMA4(uB3, a3, w0, w1, w2, w3)
        }
    }
    #pragma unroll
    for (int m = 0; m < 4; m++) {
        if (nb0 + nl + m >= NN) continue;
        float4 uA = (m == 0) ? uA0 : (m == 1) ? uA1 : (m == 2) ? uA2 : uA3;
        float4 uB = (m == 0) ? uB0 : (m == 1) ? uB1 : (m == 2) ? uB2 : uB3;
        uint2 pa, pb;
        pa.x = pack_half2(uA.x, uA.y); pa.y = pack_half2(uA.z, uA.w);
        pb.x = pack_half2(uB.x, uB.y); pb.y = pack_half2(uB.z, uB.w);
        d_th1h[(nb0 + nl + m + 1) * 16 + ch] = pa;
        d_tm1h[(nb0 + nl + m + 1) * 16 + ch] = pb;
    }

    if (blockIdx.x == 0 && t < 16) {
        d_th1h[t] = make_uint2(0u, 0u);
        d_tm1h[t] = make_uint2(0u, 0u);
    }
    if (blockIdx.x == 0 && t == 0) { d_gp1[0] = 0.f; d_gm1[0] = 0.f; }
}

// ---------------- fused alpha + gather + ELU, iteration 2 (fp16 tables) ----------
__global__ __launch_bounds__(256) void k_gather2(const int* __restrict__ se,
                                                 const int* __restrict__ bs,
                                                 const int* __restrict__ su,
                                                 const int* __restrict__ sul) {
    __shared__ float4 sbc[8][2][17];
    int t = threadIdx.x, w = t >> 5, l = t & 31, sub = l & 15, half = l >> 4;
    int n = (blockIdx.x * 8 + w) * 2 + half;

    int idx = se[n * KK + sub];
    int e   = bs[n * KK + sub];
    int j   = __ldg(&su[e]);
    float msk = (__ldg(&sul[e]) > 0) ? 1.f : 0.f;
    float v = __ldg(&d_gp1[idx]) + msk * __ldg(&d_gm1[j]);
    v = (v > 0.f) ? v : 0.2f * v;
    float alpha = softmax16((idx == 0) ? NEGINF : v);

    sbc[w][half][sub] = make_float4(alpha, __int_as_float(idx), __int_as_float(j),
                                    alpha * msk);
    __syncwarp();

    float4 acc = make_float4(0.f, 0.f, 0.f, 0.f);
    #pragma unroll
    for (int k = 0; k < KK; k++) {
        float4 b = sbc[w][half][k];
        int i  = __float_as_int(b.y);
        int jj = __float_as_int(b.z);
        uint2 hv = d_th1h[i * 16 + sub];
        float2 vA = unpack_half2(hv.x), vB = unpack_half2(hv.y);
        acc.x += b.x * vA.x; acc.y += b.x * vA.y;
        acc.z += b.x * vB.x; acc.w += b.x * vB.y;
        uint2 hu = d_tm1h[jj * 16 + sub];
        float2 uA = unpack_half2(hu.x), uB = unpack_half2(hu.y);
        acc.x += b.w * uA.x; acc.y += b.w * uA.y;
        acc.z += b.w * uB.x; acc.w += b.w * uB.y;
    }
    ELU4(acc)
    uint2 pk;
    pk.x = pack_half2(acc.x, acc.y);
    pk.y = pack_half2(acc.z, acc.w);
    d_hp2h[(n + 1) * 16 + sub] = pk;
    if (blockIdx.x == 0 && t < 16) d_hp2h[t] = make_uint2(0u, 0u);
}

// ---------------- readout (fp16 hp2 -> fp32 out) ----------------------------------
__global__ __launch_bounds__(256) void k_out(const int* __restrict__ ls,
                                             float* __restrict__ out) {
    int wid = (blockIdx.x * blockDim.x + threadIdx.x) >> 5;
    int l = threadIdx.x & 31;
    int sub = l & 15;
    int mol = wid * 2 + (l >> 4);
    if (mol >= BBATCH) return;
    const int* row = ls + mol * MAXM;
    float4 acc = make_float4(0.f, 0.f, 0.f, 0.f);
    #pragma unroll 8
    for (int m = 0; m < MAXM; m++) {
        int i = __ldg(row + m);
        uint2 hv = d_hp2h[i * 16 + sub];
        float2 vA = unpack_half2(hv.x), vB = unpack_half2(hv.y);
        acc.x += vA.x; acc.y += vA.y; acc.z += vB.x; acc.w += vB.y;
    }
    ((float4*)out)[mol * 16 + sub] = acc;
}

// ---------------- launch -----------------------------------------------------------
extern "C" void kernel_launch(void* const* d_in, const int* in_sizes, int n_in,
                              void* d_out, int out_size) {
    const float* tf  = (const float*)d_in[0];
    const float* fdg = (const float*)d_in[1];
    const float* rij = (const float*)d_in[2];
    const int*   se  = (const int*)d_in[3];
    const int*   bs  = (const int*)d_in[4];
    const int*   ls  = (const int*)d_in[5];
    const int*   su  = (const int*)d_in[6];
    const int*   sul = (const int*)d_in[7];
    const float* We  = (const float*)d_in[8];
    const float* be  = (const float*)d_in[9];
    const float* Wd  = (const float*)d_in[10];
    const float* bd  = (const float*)d_in[11];
    const float* Wg  = (const float*)d_in[12];
    const float* Wm  = (const float*)d_in[13];
    const float* ag  = (const float*)d_in[14];

    // sWg 16384 + sWm 16384 + sacc 17408 + sa9 3072 + sax 4352 = 57600 B
    int mega_smem = 2048 * 16 + 64 * 68 * 4 + 64 * 12 * 4 + 64 * 17 * 4;
    static int smem_set = 0;
    if (!smem_set) {
        cudaFuncSetAttribute(k_mega, cudaFuncAttributeMaxDynamicSharedMemorySize, mega_smem);
        smem_set = 1;
    }

    int gat_blocks = NN / 16;               // 3125
    int gemm_blocks = (NN + 63) / 64;       // 782

    k_consts<<<9, 256>>>(Wg, Wm, ag, Wd, bd, We, be);
    k_pre<<<NB_G + NB_ELOG, 256>>>(tf, fdg, rij);

    k_gather1<<<gat_blocks, 256>>>(se, bs, tf, fdg, rij);
    k_mega<<<gemm_blocks, 256, mega_smem>>>(Wg, Wm);
    k_gather2<<<gat_blocks, 256>>>(se, bs, su, sul);

    k_out<<<(BBATCH / 2 + 7) / 8, 256>>>(ls, (float*)d_out);
}